// round 1
// baseline (speedup 1.0000x reference)
#include <cuda_runtime.h>
#include <cstdint>
#include <cfloat>

#define Sdim 512
#define Bdim 64
#define Hdim 1024
#define EHdim 1024
#define Vdim 50257
#define Ktot 2048              // H + EH

// ---- scratch (no allocations allowed) ----
__device__ float g_h[Bdim * Hdim];
__device__ float g_u[Bdim * EHdim];
__device__ float g_scores[Bdim * Sdim];
__device__ float g_w[Bdim * Sdim];
__device__ float g_y[Bdim * Ktot];   // [h | context]

typedef unsigned long long ull;

__device__ __forceinline__ ull pack2(float lo, float hi) {
    ull r; asm("mov.b64 %0, {%1,%2};" : "=l"(r) : "f"(lo), "f"(hi)); return r;
}
__device__ __forceinline__ void fma2(ull& d, ull a, ull b) {
    asm("fma.rn.f32x2 %0, %1, %2, %0;" : "+l"(d) : "l"(a), "l"(b));
}
__device__ __forceinline__ float2 unpack2(ull v) {
    float2 r; asm("mov.b64 {%0,%1}, %2;" : "=f"(r.x), "=f"(r.y) : "l"(v)); return r;
}

// ---------------------------------------------------------------------------
// K1: GRU step with h0 = 0  =>  gh = b_hh.
// One warp per (b, j). 3 dots of length 1024 against W_ih rows j, 1024+j, 2048+j.
// ---------------------------------------------------------------------------
__global__ __launch_bounds__(256) void gru_kernel(
    const float* __restrict__ x, const float* __restrict__ W_ih,
    const float* __restrict__ b_ih, const float* __restrict__ b_hh,
    float* __restrict__ out_h)
{
    int gw   = (blockIdx.x * blockDim.x + threadIdx.x) >> 5;
    int lane = threadIdx.x & 31;
    int b = gw >> 10;
    int j = gw & 1023;

    const float4* xv = (const float4*)(x + (size_t)b * Hdim);
    const float4* w0 = (const float4*)(W_ih + (size_t)j * Hdim);
    const float4* w1 = (const float4*)(W_ih + (size_t)(Hdim + j) * Hdim);
    const float4* w2 = (const float4*)(W_ih + (size_t)(2 * Hdim + j) * Hdim);

    float s0 = 0.f, s1 = 0.f, s2 = 0.f;
    #pragma unroll 4
    for (int t = lane; t < Hdim / 4; t += 32) {
        float4 xx = xv[t];
        float4 a = w0[t]; s0 += xx.x*a.x + xx.y*a.y + xx.z*a.z + xx.w*a.w;
        float4 c = w1[t]; s1 += xx.x*c.x + xx.y*c.y + xx.z*c.z + xx.w*c.w;
        float4 d = w2[t]; s2 += xx.x*d.x + xx.y*d.y + xx.z*d.z + xx.w*d.w;
    }
    #pragma unroll
    for (int o = 16; o; o >>= 1) {
        s0 += __shfl_xor_sync(0xffffffffu, s0, o);
        s1 += __shfl_xor_sync(0xffffffffu, s1, o);
        s2 += __shfl_xor_sync(0xffffffffu, s2, o);
    }
    if (lane == 0) {
        float xr = s0 + b_ih[j];
        float xz = s1 + b_ih[Hdim + j];
        float xn = s2 + b_ih[2 * Hdim + j];
        float r = 1.f / (1.f + expf(-(xr + b_hh[j])));
        float z = 1.f / (1.f + expf(-(xz + b_hh[Hdim + j])));
        float n = tanhf(xn + r * b_hh[2 * Hdim + j]);
        float h = (1.f - z) * n;              // + z*h0, h0 = 0
        g_h[b * Hdim + j] = h;
        g_y[(size_t)b * Ktot + j] = h;
        out_h[b * Hdim + j] = h;
    }
}

// ---------------------------------------------------------------------------
// K2: u[b,e] = sum_h g_h[b,h] * attn_W[h, Hdim + e]
// thread per (e, b-quad): 4 b per thread to cut L2 refetch of attn_W columns.
// ---------------------------------------------------------------------------
__global__ __launch_bounds__(256) void u_kernel(const float* __restrict__ attn_W)
{
    int idx = blockIdx.x * blockDim.x + threadIdx.x;   // 16384 threads
    int e  = idx & 1023;
    int b0 = (idx >> 10) * 4;
    const float* W = attn_W + Hdim + e;                // column e of Wa_e
    float a0 = 0.f, a1 = 0.f, a2 = 0.f, a3 = 0.f;
    #pragma unroll 4
    for (int hh = 0; hh < Hdim; hh++) {
        float w = W[(size_t)hh * (Hdim + EHdim)];
        a0 += g_h[(b0 + 0) * Hdim + hh] * w;
        a1 += g_h[(b0 + 1) * Hdim + hh] * w;
        a2 += g_h[(b0 + 2) * Hdim + hh] * w;
        a3 += g_h[(b0 + 3) * Hdim + hh] * w;
    }
    g_u[(b0 + 0) * EHdim + e] = a0;
    g_u[(b0 + 1) * EHdim + e] = a1;
    g_u[(b0 + 2) * EHdim + e] = a2;
    g_u[(b0 + 3) * EHdim + e] = a3;
}

// ---------------------------------------------------------------------------
// K3: scores[b,s] = dot(enc[s,b,:], u[b,:])  (per-b constant dropped: softmax-invariant)
// warp per (b,s)
// ---------------------------------------------------------------------------
__global__ __launch_bounds__(256) void scores_kernel(const float* __restrict__ enc)
{
    int gw   = (blockIdx.x * blockDim.x + threadIdx.x) >> 5;
    int lane = threadIdx.x & 31;
    int b = gw >> 9;
    int s = gw & 511;
    const float4* ev = (const float4*)(enc + (size_t)s * (Bdim * EHdim) + (size_t)b * EHdim);
    const float4* uv = (const float4*)(g_u + (size_t)b * EHdim);
    float acc = 0.f;
    #pragma unroll 4
    for (int t = lane; t < EHdim / 4; t += 32) {
        float4 e4 = ev[t], u4 = uv[t];
        acc += e4.x*u4.x + e4.y*u4.y + e4.z*u4.z + e4.w*u4.w;
    }
    #pragma unroll
    for (int o = 16; o; o >>= 1) acc += __shfl_xor_sync(0xffffffffu, acc, o);
    if (lane == 0) g_scores[b * Sdim + s] = acc;
}

// ---------------------------------------------------------------------------
// K4: softmax over s (512) per b. Writes g_w and attn_weights output.
// ---------------------------------------------------------------------------
__global__ __launch_bounds__(256) void softmax_kernel(float* __restrict__ out_attn)
{
    int b = blockIdx.x, tid = threadIdx.x;
    __shared__ float red[8];
    __shared__ float bcast[2];

    float s0 = g_scores[b * Sdim + tid];
    float s1 = g_scores[b * Sdim + 256 + tid];

    float m = fmaxf(s0, s1);
    #pragma unroll
    for (int o = 16; o; o >>= 1) m = fmaxf(m, __shfl_xor_sync(0xffffffffu, m, o));
    if ((tid & 31) == 0) red[tid >> 5] = m;
    __syncthreads();
    if (tid < 32) {
        float v = (tid < 8) ? red[tid] : -FLT_MAX;
        #pragma unroll
        for (int o = 4; o; o >>= 1) v = fmaxf(v, __shfl_xor_sync(0xffffffffu, v, o));
        if (tid == 0) bcast[0] = v;
    }
    __syncthreads();
    float bm = bcast[0];

    float e0 = expf(s0 - bm), e1 = expf(s1 - bm);
    float sum = e0 + e1;
    #pragma unroll
    for (int o = 16; o; o >>= 1) sum += __shfl_xor_sync(0xffffffffu, sum, o);
    if ((tid & 31) == 0) red[tid >> 5] = sum;
    __syncthreads();
    if (tid < 32) {
        float v = (tid < 8) ? red[tid] : 0.f;
        #pragma unroll
        for (int o = 4; o; o >>= 1) v += __shfl_xor_sync(0xffffffffu, v, o);
        if (tid == 0) bcast[1] = v;
    }
    __syncthreads();
    float inv = 1.f / bcast[1];

    float w0 = e0 * inv, w1 = e1 * inv;
    g_w[b * Sdim + tid]       = w0;
    g_w[b * Sdim + 256 + tid] = w1;
    out_attn[b * Sdim + tid]       = w0;
    out_attn[b * Sdim + 256 + tid] = w1;
}

// ---------------------------------------------------------------------------
// K5: context[b,e] = sum_s w[b,s] * enc[s,b,e]; writes g_y[:, Hdim:]
// thread per (b,e)
// ---------------------------------------------------------------------------
__global__ __launch_bounds__(256) void context_kernel(const float* __restrict__ enc)
{
    int idx = blockIdx.x * blockDim.x + threadIdx.x;   // 65536
    int b = idx >> 10;
    int e = idx & 1023;
    const float* wrow = g_w + b * Sdim;
    const float* ep   = enc + (size_t)b * EHdim + e;
    float a0 = 0.f, a1 = 0.f;
    #pragma unroll 4
    for (int s = 0; s < Sdim; s += 2) {
        a0 += wrow[s]     * ep[(size_t)s * (Bdim * EHdim)];
        a1 += wrow[s + 1] * ep[(size_t)(s + 1) * (Bdim * EHdim)];
    }
    g_y[(size_t)b * Ktot + Hdim + e] = a0 + a1;
}

// ---------------------------------------------------------------------------
// K6: dec[b,v] = dot(y[b,:2048], out_W[v,:]) + out_b[v]
// Block tile: 64 b x 128 v, KC=16. fma.rn.f32x2 packed over b-pairs.
// Thread (bg=tx>>4 in 0..15, vg=tx&15): b in {2bg,2bg+1,2bg+32,2bg+33},
// v in {vb + vg + 16*i}, i=0..7.  w pre-packed (w,w) in smem.
// ---------------------------------------------------------------------------
#define KC 16
__global__ __launch_bounds__(256) void dec_kernel(
    const float* __restrict__ out_W, const float* __restrict__ out_b,
    float* __restrict__ dec)
{
    __shared__ ull   w_s[KC * 128];     // (w,w) pairs, [kk][v]
    __shared__ float y_s[KC * 64];      // [kk][b]

    const int tx = threadIdx.x;
    const int vg = tx & 15;
    const int bg = tx >> 4;
    const int vb = blockIdx.x * 128;

    ull acc[2][8];
    #pragma unroll
    for (int j = 0; j < 2; j++)
        #pragma unroll
        for (int i = 0; i < 8; i++) acc[j][i] = 0ull;

    for (int k0 = 0; k0 < Ktot; k0 += KC) {
        // stage W chunk (128 rows x 16 k), packed (w,w)
        {
            int r = tx >> 1, half = tx & 1;
            int v = vb + r;
            float4 f0, f1;
            if (v < Vdim) {
                const float4* wp = (const float4*)(out_W + (size_t)v * Ktot + k0 + half * 8);
                f0 = wp[0]; f1 = wp[1];
            } else {
                f0 = make_float4(0.f, 0.f, 0.f, 0.f);
                f1 = f0;
            }
            int kb = half * 8;
            w_s[(kb + 0) * 128 + r] = pack2(f0.x, f0.x);
            w_s[(kb + 1) * 128 + r] = pack2(f0.y, f0.y);
            w_s[(kb + 2) * 128 + r] = pack2(f0.z, f0.z);
            w_s[(kb + 3) * 128 + r] = pack2(f0.w, f0.w);
            w_s[(kb + 4) * 128 + r] = pack2(f1.x, f1.x);
            w_s[(kb + 5) * 128 + r] = pack2(f1.y, f1.y);
            w_s[(kb + 6) * 128 + r] = pack2(f1.z, f1.z);
            w_s[(kb + 7) * 128 + r] = pack2(f1.w, f1.w);
        }
        // stage y chunk (64 b x 16 k)
        {
            int b = tx >> 2, q = tx & 3;
            float4 yv = *(const float4*)(g_y + (size_t)b * Ktot + k0 + q * 4);
            y_s[(q * 4 + 0) * 64 + b] = yv.x;
            y_s[(q * 4 + 1) * 64 + b] = yv.y;
            y_s[(q * 4 + 2) * 64 + b] = yv.z;
            y_s[(q * 4 + 3) * 64 + b] = yv.w;
        }
        __syncthreads();

        #pragma unroll
        for (int kk = 0; kk < KC; kk++) {
            ull y0 = *(const ull*)&y_s[kk * 64 + 2 * bg];        // pair (2bg, 2bg+1)
            ull y1 = *(const ull*)&y_s[kk * 64 + 2 * bg + 32];   // pair (2bg+32, 2bg+33)
            #pragma unroll
            for (int i = 0; i < 8; i++) {
                ull w = w_s[kk * 128 + vg + 16 * i];
                fma2(acc[0][i], y0, w);
                fma2(acc[1][i], y1, w);
            }
        }
        __syncthreads();
    }

    #pragma unroll
    for (int i = 0; i < 8; i++) {
        int v = vb + vg + 16 * i;
        if (v < Vdim) {
            float bias = out_b[v];
            float2 a0 = unpack2(acc[0][i]);
            float2 a1 = unpack2(acc[1][i]);
            int r0 = 2 * bg;
            int r1 = 2 * bg + 32;
            dec[(size_t)(r0)     * Vdim + v] = a0.x + bias;
            dec[(size_t)(r0 + 1) * Vdim + v] = a0.y + bias;
            dec[(size_t)(r1)     * Vdim + v] = a1.x + bias;
            dec[(size_t)(r1 + 1) * Vdim + v] = a1.y + bias;
        }
    }
}

// ---------------------------------------------------------------------------
// K7: in-place log_softmax over V per row b
// ---------------------------------------------------------------------------
__global__ __launch_bounds__(512) void logsoftmax_kernel(float* __restrict__ dec)
{
    int b = blockIdx.x, tid = threadIdx.x;
    float* row = dec + (size_t)b * Vdim;
    __shared__ float red[16];
    __shared__ float bcast;

    float m = -FLT_MAX;
    for (int i = tid; i < Vdim; i += 512) m = fmaxf(m, row[i]);
    #pragma unroll
    for (int o = 16; o; o >>= 1) m = fmaxf(m, __shfl_xor_sync(0xffffffffu, m, o));
    if ((tid & 31) == 0) red[tid >> 5] = m;
    __syncthreads();
    if (tid < 32) {
        float v = (tid < 16) ? red[tid] : -FLT_MAX;
        #pragma unroll
        for (int o = 8; o; o >>= 1) v = fmaxf(v, __shfl_xor_sync(0xffffffffu, v, o));
        if (tid == 0) bcast = v;
    }
    __syncthreads();
    float bm = bcast;
    __syncthreads();

    float s = 0.f;
    for (int i = tid; i < Vdim; i += 512) s += expf(row[i] - bm);
    #pragma unroll
    for (int o = 16; o; o >>= 1) s += __shfl_xor_sync(0xffffffffu, s, o);
    if ((tid & 31) == 0) red[tid >> 5] = s;
    __syncthreads();
    if (tid < 32) {
        float v = (tid < 16) ? red[tid] : 0.f;
        #pragma unroll
        for (int o = 8; o; o >>= 1) v += __shfl_xor_sync(0xffffffffu, v, o);
        if (tid == 0) bcast = v;
    }
    __syncthreads();
    float lse = bm + logf(bcast);

    for (int i = tid; i < Vdim; i += 512) row[i] -= lse;
}

// ---------------------------------------------------------------------------
extern "C" void kernel_launch(void* const* d_in, const int* in_sizes, int n_in,
                              void* d_out, int out_size)
{
    const float* x      = (const float*)d_in[0];   // input_seq (1,B,I)
    const float* enc    = (const float*)d_in[1];   // encoder_outputs (S,B,EH)
    // d_in[2] = embeddings_index (unused)
    const float* W_ih   = (const float*)d_in[3];
    // d_in[4] = W_hh (unused: h0 = 0)
    const float* b_ih   = (const float*)d_in[5];
    const float* b_hh   = (const float*)d_in[6];
    const float* attn_W = (const float*)d_in[7];
    // d_in[8] = attn_b (unused: cancels in softmax)
    const float* out_W  = (const float*)d_in[9];
    const float* out_b  = (const float*)d_in[10];

    float* out = (float*)d_out;
    const size_t OFF_H    = (size_t)Bdim * Vdim;              // 3216448
    const size_t OFF_ATTN = OFF_H + (size_t)Bdim * Hdim;      // +65536

    gru_kernel<<<8192, 256>>>(x, W_ih, b_ih, b_hh, out + OFF_H);
    u_kernel<<<64, 256>>>(attn_W);
    scores_kernel<<<4096, 256>>>(enc);
    softmax_kernel<<<Bdim, 256>>>(out + OFF_ATTN);
    context_kernel<<<256, 256>>>(enc);
    dec_kernel<<<(Vdim + 127) / 128, 256>>>(out_W, out_b, out);
    logsoftmax_kernel<<<Bdim, 512>>>(out);
}

// round 2
// speedup vs baseline: 1.2688x; 1.2688x over previous
#include <cuda_runtime.h>
#include <cstdint>
#include <cfloat>

#define Sdim 512
#define Bdim 64
#define Hdim 1024
#define EHdim 1024
#define Vdim 50257
#define Ktot 2048              // H + EH

// dec GEMM tiling
#define VT   352               // v per block
#define VPT  11                // v-pairs per thread (16 vg threads * 11 = 176 pairs = 352 v)
#define KC   16                // k per chunk
#define NC   (Ktot / KC)       // 128 chunks
#define WROW 354               // padded floats per kk row (conflict-free STS/LDS)
#define DEC_GRID 143           // ceil(50257/352)

// ---- scratch (no allocations allowed) ----
__device__ float g_h[Bdim * Hdim];
__device__ float g_u[Bdim * EHdim];
__device__ float g_scores[Bdim * Sdim];
__device__ float g_w[Bdim * Sdim];
__device__ float g_y[Bdim * Ktot];                         // [h | context]
__device__ unsigned long long g_ypack[Ktot * Bdim];        // (y,y) packed, [k][b]

typedef unsigned long long ull;

__device__ __forceinline__ ull pack2(float lo, float hi) {
    ull r; asm("mov.b64 %0, {%1,%2};" : "=l"(r) : "f"(lo), "f"(hi)); return r;
}
__device__ __forceinline__ void fma2(ull& d, ull a, ull b) {
    asm("fma.rn.f32x2 %0, %1, %2, %0;" : "+l"(d) : "l"(a), "l"(b));
}
__device__ __forceinline__ float2 unpack2(ull v) {
    float2 r; asm("mov.b64 {%0,%1}, %2;" : "=f"(r.x), "=f"(r.y) : "l"(v)); return r;
}

// ---------------------------------------------------------------------------
// K1: GRU step with h0 = 0  =>  gh = b_hh.
// One warp per (j, b); j outer so the 64 warps sharing W_ih rows are adjacent
// in launch order -> W_ih streamed ~once through L2 instead of 64x.
// ---------------------------------------------------------------------------
__global__ __launch_bounds__(256) void gru_kernel(
    const float* __restrict__ x, const float* __restrict__ W_ih,
    const float* __restrict__ b_ih, const float* __restrict__ b_hh,
    float* __restrict__ out_h)
{
    int gw   = (blockIdx.x * blockDim.x + threadIdx.x) >> 5;
    int lane = threadIdx.x & 31;
    int j = gw >> 6;          // 0..1023
    int b = gw & 63;          // 0..63

    const float4* xv = (const float4*)(x + (size_t)b * Hdim);
    const float4* w0 = (const float4*)(W_ih + (size_t)j * Hdim);
    const float4* w1 = (const float4*)(W_ih + (size_t)(Hdim + j) * Hdim);
    const float4* w2 = (const float4*)(W_ih + (size_t)(2 * Hdim + j) * Hdim);

    float s0 = 0.f, s1 = 0.f, s2 = 0.f;
    #pragma unroll 4
    for (int t = lane; t < Hdim / 4; t += 32) {
        float4 xx = xv[t];
        float4 a = w0[t]; s0 += xx.x*a.x + xx.y*a.y + xx.z*a.z + xx.w*a.w;
        float4 c = w1[t]; s1 += xx.x*c.x + xx.y*c.y + xx.z*c.z + xx.w*c.w;
        float4 d = w2[t]; s2 += xx.x*d.x + xx.y*d.y + xx.z*d.z + xx.w*d.w;
    }
    #pragma unroll
    for (int o = 16; o; o >>= 1) {
        s0 += __shfl_xor_sync(0xffffffffu, s0, o);
        s1 += __shfl_xor_sync(0xffffffffu, s1, o);
        s2 += __shfl_xor_sync(0xffffffffu, s2, o);
    }
    if (lane == 0) {
        float xr = s0 + b_ih[j];
        float xz = s1 + b_ih[Hdim + j];
        float xn = s2 + b_ih[2 * Hdim + j];
        float r = 1.f / (1.f + expf(-(xr + b_hh[j])));
        float z = 1.f / (1.f + expf(-(xz + b_hh[Hdim + j])));
        float n = tanhf(xn + r * b_hh[2 * Hdim + j]);
        float h = (1.f - z) * n;              // + z*h0, h0 = 0
        g_h[b * Hdim + j] = h;
        g_y[(size_t)b * Ktot + j] = h;
        out_h[b * Hdim + j] = h;
    }
}

// ---------------------------------------------------------------------------
// K2: u[b,e] = sum_h g_h[b,h] * attn_W[h, Hdim + e]
// ---------------------------------------------------------------------------
__global__ __launch_bounds__(256) void u_kernel(const float* __restrict__ attn_W)
{
    int idx = blockIdx.x * blockDim.x + threadIdx.x;   // 16384 threads
    int e  = idx & 1023;
    int b0 = (idx >> 10) * 4;
    const float* W = attn_W + Hdim + e;                // column e of Wa_e
    float a0 = 0.f, a1 = 0.f, a2 = 0.f, a3 = 0.f;
    #pragma unroll 4
    for (int hh = 0; hh < Hdim; hh++) {
        float w = W[(size_t)hh * (Hdim + EHdim)];
        a0 += g_h[(b0 + 0) * Hdim + hh] * w;
        a1 += g_h[(b0 + 1) * Hdim + hh] * w;
        a2 += g_h[(b0 + 2) * Hdim + hh] * w;
        a3 += g_h[(b0 + 3) * Hdim + hh] * w;
    }
    g_u[(b0 + 0) * EHdim + e] = a0;
    g_u[(b0 + 1) * EHdim + e] = a1;
    g_u[(b0 + 2) * EHdim + e] = a2;
    g_u[(b0 + 3) * EHdim + e] = a3;
}

// ---------------------------------------------------------------------------
// K3: scores[b,s] = dot(enc[s,b,:], u[b,:])  (per-b const dropped: softmax-invariant)
// ---------------------------------------------------------------------------
__global__ __launch_bounds__(256) void scores_kernel(const float* __restrict__ enc)
{
    int gw   = (blockIdx.x * blockDim.x + threadIdx.x) >> 5;
    int lane = threadIdx.x & 31;
    int b = gw >> 9;
    int s = gw & 511;
    const float4* ev = (const float4*)(enc + (size_t)s * (Bdim * EHdim) + (size_t)b * EHdim);
    const float4* uv = (const float4*)(g_u + (size_t)b * EHdim);
    float acc = 0.f;
    #pragma unroll 4
    for (int t = lane; t < EHdim / 4; t += 32) {
        float4 e4 = ev[t], u4 = uv[t];
        acc += e4.x*u4.x + e4.y*u4.y + e4.z*u4.z + e4.w*u4.w;
    }
    #pragma unroll
    for (int o = 16; o; o >>= 1) acc += __shfl_xor_sync(0xffffffffu, acc, o);
    if (lane == 0) g_scores[b * Sdim + s] = acc;
}

// ---------------------------------------------------------------------------
// K4: softmax over s (512) per b
// ---------------------------------------------------------------------------
__global__ __launch_bounds__(256) void softmax_kernel(float* __restrict__ out_attn)
{
    int b = blockIdx.x, tid = threadIdx.x;
    __shared__ float red[8];
    __shared__ float bcast[2];

    float s0 = g_scores[b * Sdim + tid];
    float s1 = g_scores[b * Sdim + 256 + tid];

    float m = fmaxf(s0, s1);
    #pragma unroll
    for (int o = 16; o; o >>= 1) m = fmaxf(m, __shfl_xor_sync(0xffffffffu, m, o));
    if ((tid & 31) == 0) red[tid >> 5] = m;
    __syncthreads();
    if (tid < 32) {
        float v = (tid < 8) ? red[tid] : -FLT_MAX;
        #pragma unroll
        for (int o = 4; o; o >>= 1) v = fmaxf(v, __shfl_xor_sync(0xffffffffu, v, o));
        if (tid == 0) bcast[0] = v;
    }
    __syncthreads();
    float bm = bcast[0];

    float e0 = expf(s0 - bm), e1 = expf(s1 - bm);
    float sum = e0 + e1;
    #pragma unroll
    for (int o = 16; o; o >>= 1) sum += __shfl_xor_sync(0xffffffffu, sum, o);
    if ((tid & 31) == 0) red[tid >> 5] = sum;
    __syncthreads();
    if (tid < 32) {
        float v = (tid < 8) ? red[tid] : 0.f;
        #pragma unroll
        for (int o = 4; o; o >>= 1) v += __shfl_xor_sync(0xffffffffu, v, o);
        if (tid == 0) bcast[1] = v;
    }
    __syncthreads();
    float inv = 1.f / bcast[1];

    float w0 = e0 * inv, w1 = e1 * inv;
    g_w[b * Sdim + tid]       = w0;
    g_w[b * Sdim + 256 + tid] = w1;
    out_attn[b * Sdim + tid]       = w0;
    out_attn[b * Sdim + 256 + tid] = w1;
}

// ---------------------------------------------------------------------------
// K5: context[b,e] = sum_s w[b,s] * enc[s,b,e]; writes g_y[:, Hdim:]
// ---------------------------------------------------------------------------
__global__ __launch_bounds__(256) void context_kernel(const float* __restrict__ enc)
{
    int idx = blockIdx.x * blockDim.x + threadIdx.x;   // 65536
    int b = idx >> 10;
    int e = idx & 1023;
    const float* wrow = g_w + b * Sdim;
    const float* ep   = enc + (size_t)b * EHdim + e;
    float a0 = 0.f, a1 = 0.f;
    #pragma unroll 4
    for (int s = 0; s < Sdim; s += 2) {
        a0 += wrow[s]     * ep[(size_t)s * (Bdim * EHdim)];
        a1 += wrow[s + 1] * ep[(size_t)(s + 1) * (Bdim * EHdim)];
    }
    g_y[(size_t)b * Ktot + Hdim + e] = a0 + a1;
}

// ---------------------------------------------------------------------------
// K5b: pack y into (y,y) ull, transposed to [k][b] for flat dec staging
// ---------------------------------------------------------------------------
__global__ __launch_bounds__(256) void pack_y_kernel()
{
    int idx = blockIdx.x * 256 + threadIdx.x;    // 131072
    int k = idx >> 6, b = idx & 63;
    float y = g_y[(size_t)b * Ktot + k];
    g_ypack[idx] = pack2(y, y);
}

// ---------------------------------------------------------------------------
// K6: dec[b,v] = dot(y[b,:2048], out_W[v,:]) + out_b[v]
// Tile 64b x 352v. Double-buffered smem, register-prefetched global loads.
// Thread (vg=tx&15, bg=tx>>4): 11 v-pairs x 4 b, 44 fma.rn.f32x2 per kk.
// w_s layout [kk][v] plain floats (LDS.64 of even v = natural pair),
// row stride 354 floats -> conflict-free STS (4j+vl distinct) and LDS.
// ---------------------------------------------------------------------------
__global__ __launch_bounds__(256, 1) void dec_kernel(
    const float* __restrict__ out_W, const float* __restrict__ out_b,
    float* __restrict__ dec)
{
    extern __shared__ char dsm[];
    float* w_s = (float*)dsm;                          // [2][KC][WROW]
    ull*   y_s = (ull*)(dsm + 2 * KC * WROW * 4);      // [2][KC][64]

    const int tx = threadIdx.x;
    const int vg = tx & 15;
    const int bg = tx >> 4;
    const int vb = blockIdx.x * VT;

    ull acc[4][VPT];
    #pragma unroll
    for (int j = 0; j < 4; j++)
        #pragma unroll
        for (int i = 0; i < VPT; i++) acc[j][i] = 0ull;

    float2 wreg[VPT];
    uint4  yreg0, yreg1;

    // prologue: chunk 0 -> regs -> smem buf 0
    {
        const int k0 = 0;
        #pragma unroll
        for (int i = 0; i < VPT; i++) {
            int q = tx + 256 * i;
            int vl = q >> 3, jj = q & 7;
            int v = vb + vl;
            wreg[i] = (v < Vdim)
                ? *(const float2*)(out_W + (size_t)v * Ktot + k0 + 2 * jj)
                : make_float2(0.f, 0.f);
        }
        const uint4* yp = (const uint4*)(g_ypack + (size_t)k0 * Bdim);
        yreg0 = yp[tx]; yreg1 = yp[tx + 256];

        #pragma unroll
        for (int i = 0; i < VPT; i++) {
            int q = tx + 256 * i;
            int vl = q >> 3, jj = q & 7;
            w_s[(2 * jj) * WROW + vl]     = wreg[i].x;
            w_s[(2 * jj + 1) * WROW + vl] = wreg[i].y;
        }
        uint4* yb = (uint4*)y_s;
        yb[tx] = yreg0; yb[tx + 256] = yreg1;
    }
    __syncthreads();

    for (int c = 0; c < NC; c++) {
        const int buf = c & 1;

        // prefetch chunk c+1 into registers (hidden under compute)
        if (c + 1 < NC) {
            const int k0 = (c + 1) * KC;
            #pragma unroll
            for (int i = 0; i < VPT; i++) {
                int q = tx + 256 * i;
                int vl = q >> 3, jj = q & 7;
                int v = vb + vl;
                wreg[i] = (v < Vdim)
                    ? *(const float2*)(out_W + (size_t)v * Ktot + k0 + 2 * jj)
                    : make_float2(0.f, 0.f);
            }
            const uint4* yp = (const uint4*)(g_ypack + (size_t)k0 * Bdim);
            yreg0 = yp[tx]; yreg1 = yp[tx + 256];
        }

        // compute on buf
        const float* wb = w_s + buf * KC * WROW;
        const ull*   yb = y_s + buf * KC * Bdim;
        #pragma unroll
        for (int kk = 0; kk < KC; kk++) {
            ull yv[4];
            #pragma unroll
            for (int j = 0; j < 4; j++) yv[j] = yb[kk * Bdim + 4 * bg + j];
            #pragma unroll
            for (int i = 0; i < VPT; i++) {
                ull w = *(const ull*)(wb + kk * WROW + 2 * (vg + 16 * i));
                #pragma unroll
                for (int j = 0; j < 4; j++) fma2(acc[j][i], yv[j], w);
            }
        }

        // store prefetched chunk into the other buffer (no hazard: different buf)
        if (c + 1 < NC) {
            const int nbuf = (c + 1) & 1;
            float* wd = w_s + nbuf * KC * WROW;
            #pragma unroll
            for (int i = 0; i < VPT; i++) {
                int q = tx + 256 * i;
                int vl = q >> 3, jj = q & 7;
                wd[(2 * jj) * WROW + vl]     = wreg[i].x;
                wd[(2 * jj + 1) * WROW + vl] = wreg[i].y;
            }
            uint4* yd = (uint4*)(y_s + nbuf * KC * Bdim);
            yd[tx] = yreg0; yd[tx + 256] = yreg1;
        }
        __syncthreads();
    }

    // epilogue
    #pragma unroll
    for (int i = 0; i < VPT; i++) {
        int v0 = vb + 2 * (vg + 16 * i);
        int v1 = v0 + 1;
        float bias0 = (v0 < Vdim) ? out_b[v0] : 0.f;
        float bias1 = (v1 < Vdim) ? out_b[v1] : 0.f;
        #pragma unroll
        for (int j = 0; j < 4; j++) {
            float2 a = unpack2(acc[j][i]);
            int b = 4 * bg + j;
            if (v0 < Vdim) dec[(size_t)b * Vdim + v0] = a.x + bias0;
            if (v1 < Vdim) dec[(size_t)b * Vdim + v1] = a.y + bias1;
        }
    }
}

// ---------------------------------------------------------------------------
// K7: in-place log_softmax over V per row b
// ---------------------------------------------------------------------------
__global__ __launch_bounds__(512) void logsoftmax_kernel(float* __restrict__ dec)
{
    int b = blockIdx.x, tid = threadIdx.x;
    float* row = dec + (size_t)b * Vdim;
    __shared__ float red[16];
    __shared__ float bcast;

    float m = -FLT_MAX;
    for (int i = tid; i < Vdim; i += 512) m = fmaxf(m, row[i]);
    #pragma unroll
    for (int o = 16; o; o >>= 1) m = fmaxf(m, __shfl_xor_sync(0xffffffffu, m, o));
    if ((tid & 31) == 0) red[tid >> 5] = m;
    __syncthreads();
    if (tid < 32) {
        float v = (tid < 16) ? red[tid] : -FLT_MAX;
        #pragma unroll
        for (int o = 8; o; o >>= 1) v = fmaxf(v, __shfl_xor_sync(0xffffffffu, v, o));
        if (tid == 0) bcast = v;
    }
    __syncthreads();
    float bm = bcast;
    __syncthreads();

    float s = 0.f;
    for (int i = tid; i < Vdim; i += 512) s += expf(row[i] - bm);
    #pragma unroll
    for (int o = 16; o; o >>= 1) s += __shfl_xor_sync(0xffffffffu, s, o);
    if ((tid & 31) == 0) red[tid >> 5] = s;
    __syncthreads();
    if (tid < 32) {
        float v = (tid < 16) ? red[tid] : 0.f;
        #pragma unroll
        for (int o = 8; o; o >>= 1) v += __shfl_xor_sync(0xffffffffu, v, o);
        if (tid == 0) bcast = v;
    }
    __syncthreads();
    float lse = bm + logf(bcast);

    for (int i = tid; i < Vdim; i += 512) row[i] -= lse;
}

// ---------------------------------------------------------------------------
extern "C" void kernel_launch(void* const* d_in, const int* in_sizes, int n_in,
                              void* d_out, int out_size)
{
    const float* x      = (const float*)d_in[0];   // input_seq (1,B,I)
    const float* enc    = (const float*)d_in[1];   // encoder_outputs (S,B,EH)
    const float* W_ih   = (const float*)d_in[3];
    const float* b_ih   = (const float*)d_in[5];
    const float* b_hh   = (const float*)d_in[6];
    const float* attn_W = (const float*)d_in[7];
    const float* out_W  = (const float*)d_in[9];
    const float* out_b  = (const float*)d_in[10];

    float* out = (float*)d_out;
    const size_t OFF_H    = (size_t)Bdim * Vdim;
    const size_t OFF_ATTN = OFF_H + (size_t)Bdim * Hdim;

    const int dec_smem = 2 * KC * WROW * 4 + 2 * KC * Bdim * 8;  // 61696 B
    cudaFuncSetAttribute(dec_kernel, cudaFuncAttributeMaxDynamicSharedMemorySize, dec_smem);

    gru_kernel<<<8192, 256>>>(x, W_ih, b_ih, b_hh, out + OFF_H);
    u_kernel<<<64, 256>>>(attn_W);
    scores_kernel<<<4096, 256>>>(enc);
    softmax_kernel<<<Bdim, 256>>>(out + OFF_ATTN);
    context_kernel<<<256, 256>>>(enc);
    pack_y_kernel<<<512, 256>>>();
    dec_kernel<<<DEC_GRID, 256, dec_smem>>>(out_W, out_b, out);
    logsoftmax_kernel<<<Bdim, 512>>>(out);
}

// round 3
// speedup vs baseline: 1.3048x; 1.0283x over previous
#include <cuda_runtime.h>
#include <cstdint>
#include <cfloat>

#define Sdim 512
#define Bdim 64
#define Hdim 1024
#define EHdim 1024
#define Vdim 50257
#define Ktot 2048              // H + EH

// dec GEMM tiling
#define VT   352               // v per block
#define VPT  11                // v-pairs per thread (16 vg threads * 11 = 176 pairs = 352 v)
#define KC   16                // k per chunk
#define NC   (Ktot / KC)       // 128 chunks
#define WROW 354               // padded floats per kk row (conflict-free STS/LDS)
#define DEC_GRID 143           // ceil(50257/352)

// ---- scratch (no allocations allowed) ----
__device__ float g_h[Bdim * Hdim];
__device__ float g_u[Bdim * EHdim];
__device__ float g_scores[Bdim * Sdim];
__device__ float g_w[Bdim * Sdim];
__device__ float g_y[Bdim * Ktot];                         // [h | context]
__device__ unsigned long long g_ypack[Ktot * Bdim];        // (y,y) packed, [k][b]

typedef unsigned long long ull;

__device__ __forceinline__ ull pack2(float lo, float hi) {
    ull r; asm("mov.b64 %0, {%1,%2};" : "=l"(r) : "f"(lo), "f"(hi)); return r;
}
__device__ __forceinline__ void fma2(ull& d, ull a, ull b) {
    asm("fma.rn.f32x2 %0, %1, %2, %0;" : "+l"(d) : "l"(a), "l"(b));
}
__device__ __forceinline__ float2 unpack2(ull v) {
    float2 r; asm("mov.b64 {%0,%1}, %2;" : "=f"(r.x), "=f"(r.y) : "l"(v)); return r;
}

// ---------------------------------------------------------------------------
// K1: GRU step with h0 = 0  =>  gh = b_hh.
// One warp per (j, b); j outer so the 64 warps sharing W_ih rows are adjacent
// in launch order -> W_ih streamed ~once through L2 instead of 64x.
// ---------------------------------------------------------------------------
__global__ __launch_bounds__(256) void gru_kernel(
    const float* __restrict__ x, const float* __restrict__ W_ih,
    const float* __restrict__ b_ih, const float* __restrict__ b_hh,
    float* __restrict__ out_h)
{
    int gw   = (blockIdx.x * blockDim.x + threadIdx.x) >> 5;
    int lane = threadIdx.x & 31;
    int j = gw >> 6;          // 0..1023
    int b = gw & 63;          // 0..63

    const float4* xv = (const float4*)(x + (size_t)b * Hdim);
    const float4* w0 = (const float4*)(W_ih + (size_t)j * Hdim);
    const float4* w1 = (const float4*)(W_ih + (size_t)(Hdim + j) * Hdim);
    const float4* w2 = (const float4*)(W_ih + (size_t)(2 * Hdim + j) * Hdim);

    float s0 = 0.f, s1 = 0.f, s2 = 0.f;
    #pragma unroll 4
    for (int t = lane; t < Hdim / 4; t += 32) {
        float4 xx = xv[t];
        float4 a = w0[t]; s0 += xx.x*a.x + xx.y*a.y + xx.z*a.z + xx.w*a.w;
        float4 c = w1[t]; s1 += xx.x*c.x + xx.y*c.y + xx.z*c.z + xx.w*c.w;
        float4 d = w2[t]; s2 += xx.x*d.x + xx.y*d.y + xx.z*d.z + xx.w*d.w;
    }
    #pragma unroll
    for (int o = 16; o; o >>= 1) {
        s0 += __shfl_xor_sync(0xffffffffu, s0, o);
        s1 += __shfl_xor_sync(0xffffffffu, s1, o);
        s2 += __shfl_xor_sync(0xffffffffu, s2, o);
    }
    if (lane == 0) {
        float xr = s0 + b_ih[j];
        float xz = s1 + b_ih[Hdim + j];
        float xn = s2 + b_ih[2 * Hdim + j];
        float r = 1.f / (1.f + expf(-(xr + b_hh[j])));
        float z = 1.f / (1.f + expf(-(xz + b_hh[Hdim + j])));
        float n = tanhf(xn + r * b_hh[2 * Hdim + j]);
        float h = (1.f - z) * n;              // + z*h0, h0 = 0
        g_h[b * Hdim + j] = h;
        g_y[(size_t)b * Ktot + j] = h;
        out_h[b * Hdim + j] = h;
    }
}

// ---------------------------------------------------------------------------
// K2: u[b,e] = sum_h g_h[b,h] * attn_W[h, Hdim + e]
// ---------------------------------------------------------------------------
__global__ __launch_bounds__(256) void u_kernel(const float* __restrict__ attn_W)
{
    int idx = blockIdx.x * blockDim.x + threadIdx.x;   // 16384 threads
    int e  = idx & 1023;
    int b0 = (idx >> 10) * 4;
    const float* W = attn_W + Hdim + e;                // column e of Wa_e
    float a0 = 0.f, a1 = 0.f, a2 = 0.f, a3 = 0.f;
    #pragma unroll 4
    for (int hh = 0; hh < Hdim; hh++) {
        float w = W[(size_t)hh * (Hdim + EHdim)];
        a0 += g_h[(b0 + 0) * Hdim + hh] * w;
        a1 += g_h[(b0 + 1) * Hdim + hh] * w;
        a2 += g_h[(b0 + 2) * Hdim + hh] * w;
        a3 += g_h[(b0 + 3) * Hdim + hh] * w;
    }
    g_u[(b0 + 0) * EHdim + e] = a0;
    g_u[(b0 + 1) * EHdim + e] = a1;
    g_u[(b0 + 2) * EHdim + e] = a2;
    g_u[(b0 + 3) * EHdim + e] = a3;
}

// ---------------------------------------------------------------------------
// K3: scores[b,s] = dot(enc[s,b,:], u[b,:])  (per-b const dropped: softmax-invariant)
// ---------------------------------------------------------------------------
__global__ __launch_bounds__(256) void scores_kernel(const float* __restrict__ enc)
{
    int gw   = (blockIdx.x * blockDim.x + threadIdx.x) >> 5;
    int lane = threadIdx.x & 31;
    int b = gw >> 9;
    int s = gw & 511;
    const float4* ev = (const float4*)(enc + (size_t)s * (Bdim * EHdim) + (size_t)b * EHdim);
    const float4* uv = (const float4*)(g_u + (size_t)b * EHdim);
    float acc = 0.f;
    #pragma unroll 4
    for (int t = lane; t < EHdim / 4; t += 32) {
        float4 e4 = ev[t], u4 = uv[t];
        acc += e4.x*u4.x + e4.y*u4.y + e4.z*u4.z + e4.w*u4.w;
    }
    #pragma unroll
    for (int o = 16; o; o >>= 1) acc += __shfl_xor_sync(0xffffffffu, acc, o);
    if (lane == 0) g_scores[b * Sdim + s] = acc;
}

// ---------------------------------------------------------------------------
// K4: softmax over s (512) per b
// ---------------------------------------------------------------------------
__global__ __launch_bounds__(256) void softmax_kernel(float* __restrict__ out_attn)
{
    int b = blockIdx.x, tid = threadIdx.x;
    __shared__ float red[8];
    __shared__ float bcast[2];

    float s0 = g_scores[b * Sdim + tid];
    float s1 = g_scores[b * Sdim + 256 + tid];

    float m = fmaxf(s0, s1);
    #pragma unroll
    for (int o = 16; o; o >>= 1) m = fmaxf(m, __shfl_xor_sync(0xffffffffu, m, o));
    if ((tid & 31) == 0) red[tid >> 5] = m;
    __syncthreads();
    if (tid < 32) {
        float v = (tid < 8) ? red[tid] : -FLT_MAX;
        #pragma unroll
        for (int o = 4; o; o >>= 1) v = fmaxf(v, __shfl_xor_sync(0xffffffffu, v, o));
        if (tid == 0) bcast[0] = v;
    }
    __syncthreads();
    float bm = bcast[0];

    float e0 = expf(s0 - bm), e1 = expf(s1 - bm);
    float sum = e0 + e1;
    #pragma unroll
    for (int o = 16; o; o >>= 1) sum += __shfl_xor_sync(0xffffffffu, sum, o);
    if ((tid & 31) == 0) red[tid >> 5] = sum;
    __syncthreads();
    if (tid < 32) {
        float v = (tid < 8) ? red[tid] : 0.f;
        #pragma unroll
        for (int o = 4; o; o >>= 1) v += __shfl_xor_sync(0xffffffffu, v, o);
        if (tid == 0) bcast[1] = v;
    }
    __syncthreads();
    float inv = 1.f / bcast[1];

    float w0 = e0 * inv, w1 = e1 * inv;
    g_w[b * Sdim + tid]       = w0;
    g_w[b * Sdim + 256 + tid] = w1;
    out_attn[b * Sdim + tid]       = w0;
    out_attn[b * Sdim + 256 + tid] = w1;
}

// ---------------------------------------------------------------------------
// K5: context[b,e] = sum_s w[b,s] * enc[s,b,e]; writes g_y[:, Hdim:]
// ---------------------------------------------------------------------------
__global__ __launch_bounds__(256) void context_kernel(const float* __restrict__ enc)
{
    int idx = blockIdx.x * blockDim.x + threadIdx.x;   // 65536
    int b = idx >> 10;
    int e = idx & 1023;
    const float* wrow = g_w + b * Sdim;
    const float* ep   = enc + (size_t)b * EHdim + e;
    float a0 = 0.f, a1 = 0.f;
    #pragma unroll 4
    for (int s = 0; s < Sdim; s += 2) {
        a0 += wrow[s]     * ep[(size_t)s * (Bdim * EHdim)];
        a1 += wrow[s + 1] * ep[(size_t)(s + 1) * (Bdim * EHdim)];
    }
    g_y[(size_t)b * Ktot + Hdim + e] = a0 + a1;
}

// ---------------------------------------------------------------------------
// K5b: pack y into (y,y) ull, transposed to [k][b] for flat dec staging
// ---------------------------------------------------------------------------
__global__ __launch_bounds__(256) void pack_y_kernel()
{
    int idx = blockIdx.x * 256 + threadIdx.x;    // 131072
    int k = idx >> 6, b = idx & 63;
    float y = g_y[(size_t)b * Ktot + k];
    g_ypack[idx] = pack2(y, y);
}

// ---------------------------------------------------------------------------
// K6: dec[b,v] = dot(y[b,:2048], out_W[v,:]) + out_b[v]
// Tile 64b x 352v. Double-buffered smem, register-prefetched global loads.
// Thread (vg=tx&15, bg=tx>>4): 11 v-pairs x 4 b, 44 fma.rn.f32x2 per kk.
// w_s layout [kk][v] plain floats (LDS.64 of even v = natural pair),
// row stride 354 floats -> conflict-free STS (4j+vl distinct) and LDS.
// ---------------------------------------------------------------------------
__global__ __launch_bounds__(256, 1) void dec_kernel(
    const float* __restrict__ out_W, const float* __restrict__ out_b,
    float* __restrict__ dec)
{
    extern __shared__ char dsm[];
    float* w_s = (float*)dsm;                          // [2][KC][WROW]
    ull*   y_s = (ull*)(dsm + 2 * KC * WROW * 4);      // [2][KC][64]

    const int tx = threadIdx.x;
    const int vg = tx & 15;
    const int bg = tx >> 4;
    const int vb = blockIdx.x * VT;

    ull acc[4][VPT];
    #pragma unroll
    for (int j = 0; j < 4; j++)
        #pragma unroll
        for (int i = 0; i < VPT; i++) acc[j][i] = 0ull;

    float2 wreg[VPT];
    uint4  yreg0, yreg1;

    // prologue: chunk 0 -> regs -> smem buf 0
    {
        const int k0 = 0;
        #pragma unroll
        for (int i = 0; i < VPT; i++) {
            int q = tx + 256 * i;
            int vl = q >> 3, jj = q & 7;
            int v = vb + vl;
            wreg[i] = (v < Vdim)
                ? *(const float2*)(out_W + (size_t)v * Ktot + k0 + 2 * jj)
                : make_float2(0.f, 0.f);
        }
        const uint4* yp = (const uint4*)(g_ypack + (size_t)k0 * Bdim);
        yreg0 = yp[tx]; yreg1 = yp[tx + 256];

        #pragma unroll
        for (int i = 0; i < VPT; i++) {
            int q = tx + 256 * i;
            int vl = q >> 3, jj = q & 7;
            w_s[(2 * jj) * WROW + vl]     = wreg[i].x;
            w_s[(2 * jj + 1) * WROW + vl] = wreg[i].y;
        }
        uint4* yb = (uint4*)y_s;
        yb[tx] = yreg0; yb[tx + 256] = yreg1;
    }
    __syncthreads();

    for (int c = 0; c < NC; c++) {
        const int buf = c & 1;

        // prefetch chunk c+1 into registers (hidden under compute)
        if (c + 1 < NC) {
            const int k0 = (c + 1) * KC;
            #pragma unroll
            for (int i = 0; i < VPT; i++) {
                int q = tx + 256 * i;
                int vl = q >> 3, jj = q & 7;
                int v = vb + vl;
                wreg[i] = (v < Vdim)
                    ? *(const float2*)(out_W + (size_t)v * Ktot + k0 + 2 * jj)
                    : make_float2(0.f, 0.f);
            }
            const uint4* yp = (const uint4*)(g_ypack + (size_t)k0 * Bdim);
            yreg0 = yp[tx]; yreg1 = yp[tx + 256];
        }

        // compute on buf
        const float* wb = w_s + buf * KC * WROW;
        const ull*   yb = y_s + buf * KC * Bdim;
        #pragma unroll
        for (int kk = 0; kk < KC; kk++) {
            ull yv[4];
            #pragma unroll
            for (int j = 0; j < 4; j++) yv[j] = yb[kk * Bdim + 4 * bg + j];
            #pragma unroll
            for (int i = 0; i < VPT; i++) {
                ull w = *(const ull*)(wb + kk * WROW + 2 * (vg + 16 * i));
                #pragma unroll
                for (int j = 0; j < 4; j++) fma2(acc[j][i], yv[j], w);
            }
        }

        // store prefetched chunk into the other buffer (no hazard: different buf)
        if (c + 1 < NC) {
            const int nbuf = (c + 1) & 1;
            float* wd = w_s + nbuf * KC * WROW;
            #pragma unroll
            for (int i = 0; i < VPT; i++) {
                int q = tx + 256 * i;
                int vl = q >> 3, jj = q & 7;
                wd[(2 * jj) * WROW + vl]     = wreg[i].x;
                wd[(2 * jj + 1) * WROW + vl] = wreg[i].y;
            }
            uint4* yd = (uint4*)(y_s + nbuf * KC * Bdim);
            yd[tx] = yreg0; yd[tx + 256] = yreg1;
        }
        __syncthreads();
    }

    // epilogue
    #pragma unroll
    for (int i = 0; i < VPT; i++) {
        int v0 = vb + 2 * (vg + 16 * i);
        int v1 = v0 + 1;
        float bias0 = (v0 < Vdim) ? out_b[v0] : 0.f;
        float bias1 = (v1 < Vdim) ? out_b[v1] : 0.f;
        #pragma unroll
        for (int j = 0; j < 4; j++) {
            float2 a = unpack2(acc[j][i]);
            int b = 4 * bg + j;
            if (v0 < Vdim) dec[(size_t)b * Vdim + v0] = a.x + bias0;
            if (v1 < Vdim) dec[(size_t)b * Vdim + v1] = a.y + bias1;
        }
    }
}

// ---------------------------------------------------------------------------
// K7: in-place log_softmax over V per row b
// ---------------------------------------------------------------------------
__global__ __launch_bounds__(512) void logsoftmax_kernel(float* __restrict__ dec)
{
    int b = blockIdx.x, tid = threadIdx.x;
    float* row = dec + (size_t)b * Vdim;
    __shared__ float red[16];
    __shared__ float bcast;

    float m = -FLT_MAX;
    for (int i = tid; i < Vdim; i += 512) m = fmaxf(m, row[i]);
    #pragma unroll
    for (int o = 16; o; o >>= 1) m = fmaxf(m, __shfl_xor_sync(0xffffffffu, m, o));
    if ((tid & 31) == 0) red[tid >> 5] = m;
    __syncthreads();
    if (tid < 32) {
        float v = (tid < 16) ? red[tid] : -FLT_MAX;
        #pragma unroll
        for (int o = 8; o; o >>= 1) v = fmaxf(v, __shfl_xor_sync(0xffffffffu, v, o));
        if (tid == 0) bcast = v;
    }
    __syncthreads();
    float bm = bcast;
    __syncthreads();

    float s = 0.f;
    for (int i = tid; i < Vdim; i += 512) s += expf(row[i] - bm);
    #pragma unroll
    for (int o = 16; o; o >>= 1) s += __shfl_xor_sync(0xffffffffu, s, o);
    if ((tid & 31) == 0) red[tid >> 5] = s;
    __syncthreads();
    if (tid < 32) {
        float v = (tid < 16) ? red[tid] : 0.f;
        #pragma unroll
        for (int o = 8; o; o >>= 1) v += __shfl_xor_sync(0xffffffffu, v, o);
        if (tid == 0) bcast = v;
    }
    __syncthreads();
    float lse = bm + logf(bcast);

    for (int i = tid; i < Vdim; i += 512) row[i] -= lse;
}

// ---------------------------------------------------------------------------
extern "C" void kernel_launch(void* const* d_in, const int* in_sizes, int n_in,
                              void* d_out, int out_size)
{
    const float* x      = (const float*)d_in[0];   // input_seq (1,B,I)
    const float* enc    = (const float*)d_in[1];   // encoder_outputs (S,B,EH)
    const float* W_ih   = (const float*)d_in[3];
    const float* b_ih   = (const float*)d_in[5];
    const float* b_hh   = (const float*)d_in[6];
    const float* attn_W = (const float*)d_in[7];
    const float* out_W  = (const float*)d_in[9];
    const float* out_b  = (const float*)d_in[10];

    float* out = (float*)d_out;
    const size_t OFF_H    = (size_t)Bdim * Vdim;
    const size_t OFF_ATTN = OFF_H + (size_t)Bdim * Hdim;

    const int dec_smem = 2 * KC * WROW * 4 + 2 * KC * Bdim * 8;  // 61696 B
    cudaFuncSetAttribute(dec_kernel, cudaFuncAttributeMaxDynamicSharedMemorySize, dec_smem);

    gru_kernel<<<8192, 256>>>(x, W_ih, b_ih, b_hh, out + OFF_H);
    u_kernel<<<64, 256>>>(attn_W);
    scores_kernel<<<4096, 256>>>(enc);
    softmax_kernel<<<Bdim, 256>>>(out + OFF_ATTN);
    context_kernel<<<256, 256>>>(enc);
    pack_y_kernel<<<512, 256>>>();
    dec_kernel<<<DEC_GRID, 256, dec_smem>>>(out_W, out_b, out);
    logsoftmax_kernel<<<Bdim, 512>>>(out);
}

// round 5
// speedup vs baseline: 1.7566x; 1.3463x over previous
#include <cuda_runtime.h>
#include <cstdint>
#include <cfloat>

#define Sdim 512
#define Bdim 64
#define Hdim 1024
#define EHdim 1024
#define Vdim 50257
#define Ktot 2048              // H + EH

// ---- scratch (no allocations allowed) ----
__device__ float g_h[Bdim * Hdim];
__device__ float g_u[Bdim * EHdim];
__device__ float g_scores[Bdim * Sdim];
__device__ float g_w[Bdim * Sdim];
__device__ float g_y[Bdim * Ktot];   // [h | context], K-major per b

// ============================================================================
// sm_80-class PTX helpers (safe under .target sm_103 — no 'a' features)
// ============================================================================
__device__ __forceinline__ uint32_t smem_to_u32(const void* p) {
    uint32_t a;
    asm("{ .reg .u64 t; cvta.to.shared.u64 t, %1; cvt.u32.u64 %0, t; }" : "=r"(a) : "l"(p));
    return a;
}
__device__ __forceinline__ void cp_async16(uint32_t dst, const void* src) {
    asm volatile("cp.async.ca.shared.global [%0], [%1], 16;" :: "r"(dst), "l"(src));
}
__device__ __forceinline__ void cp_async16_zfill(uint32_t dst, const void* src, int src_bytes) {
    asm volatile("cp.async.ca.shared.global [%0], [%1], 16, %2;"
                 :: "r"(dst), "l"(src), "r"(src_bytes));
}
#define CP_COMMIT() asm volatile("cp.async.commit_group;" ::: "memory")
#define CP_WAIT(n)  asm volatile("cp.async.wait_group %0;" :: "n"(n) : "memory")

__device__ __forceinline__ uint32_t f2tf32(float f) {
    uint32_t r; asm("cvt.rna.tf32.f32 %0, %1;" : "=r"(r) : "f"(f)); return r;
}
__device__ __forceinline__ void mma_tf32(float* c, const uint32_t* a, const uint32_t* b) {
    asm volatile("mma.sync.aligned.m16n8k8.row.col.f32.tf32.tf32.f32 "
        "{%0,%1,%2,%3}, {%4,%5,%6,%7}, {%8,%9}, {%0,%1,%2,%3};"
        : "+f"(c[0]), "+f"(c[1]), "+f"(c[2]), "+f"(c[3])
        : "r"(a[0]), "r"(a[1]), "r"(a[2]), "r"(a[3]), "r"(b[0]), "r"(b[1]));
}

// ---------------------------------------------------------------------------
// K1: GRU with h0=0 => gh = b_hh. Tiled GEMM: block = 8 j x 64 b, K via smem.
// W_ih streamed exactly once (12.6 MB DRAM, no L2 amplification).
// ---------------------------------------------------------------------------
__global__ __launch_bounds__(256) void gru_kernel(
    const float* __restrict__ x, const float* __restrict__ W_ih,
    const float* __restrict__ b_ih, const float* __restrict__ b_hh,
    float* __restrict__ out_h)
{
    __shared__ float w_s[24][33];   // rows = gate*8 + jl, cols = kk (pad 33)
    __shared__ float x_s[32][65];   // [kk][b] (pad 65)

    const int t  = threadIdx.x;
    const int j0 = blockIdx.x * 8;
    const int jj = t & 7;
    const int bg = t >> 3;          // 0..31, b-pair

    float a00 = 0.f, a01 = 0.f, a10 = 0.f, a11 = 0.f, a20 = 0.f, a21 = 0.f;

    for (int k0 = 0; k0 < Hdim; k0 += 32) {
        if (t < 192) {
            int r = t >> 3, f4 = t & 7;
            int g = r >> 3, jl = r & 7;
            float4 w = *(const float4*)(W_ih + (size_t)(g * Hdim + j0 + jl) * Hdim + k0 + 4 * f4);
            w_s[r][4 * f4 + 0] = w.x; w_s[r][4 * f4 + 1] = w.y;
            w_s[r][4 * f4 + 2] = w.z; w_s[r][4 * f4 + 3] = w.w;
        }
        #pragma unroll
        for (int i = 0; i < 2; i++) {
            int idx = t + 256 * i;
            int b = idx >> 3, q = idx & 7;
            float4 xv = *(const float4*)(x + (size_t)b * Hdim + k0 + 4 * q);
            x_s[4 * q + 0][b] = xv.x; x_s[4 * q + 1][b] = xv.y;
            x_s[4 * q + 2][b] = xv.z; x_s[4 * q + 3][b] = xv.w;
        }
        __syncthreads();
        #pragma unroll
        for (int kk = 0; kk < 32; kk++) {
            float x0 = x_s[kk][2 * bg], x1 = x_s[kk][2 * bg + 1];
            float w0 = w_s[jj][kk], w1 = w_s[8 + jj][kk], w2 = w_s[16 + jj][kk];
            a00 += w0 * x0; a01 += w0 * x1;
            a10 += w1 * x0; a11 += w1 * x1;
            a20 += w2 * x0; a21 += w2 * x1;
        }
        __syncthreads();
    }

    int j = j0 + jj;
    float bi0 = b_ih[j], bi1 = b_ih[Hdim + j], bi2 = b_ih[2 * Hdim + j];
    float bh0 = b_hh[j], bh1 = b_hh[Hdim + j], bh2 = b_hh[2 * Hdim + j];
    #pragma unroll
    for (int q = 0; q < 2; q++) {
        int b = 2 * bg + q;
        float xr = (q ? a01 : a00) + bi0;
        float xz = (q ? a11 : a10) + bi1;
        float xn = (q ? a21 : a20) + bi2;
        float r = 1.f / (1.f + expf(-(xr + bh0)));
        float z = 1.f / (1.f + expf(-(xz + bh1)));
        float n = tanhf(xn + r * bh2);
        float h = (1.f - z) * n;               // + z*h0, h0 = 0
        g_h[b * Hdim + j] = h;
        g_y[(size_t)b * Ktot + j] = h;
        out_h[b * Hdim + j] = h;
    }
}

// ---------------------------------------------------------------------------
// K2: u[b,e] = sum_h g_h[b,h] * attn_W[h, Hdim + e]
// ---------------------------------------------------------------------------
__global__ __launch_bounds__(256) void u_kernel(const float* __restrict__ attn_W)
{
    int idx = blockIdx.x * blockDim.x + threadIdx.x;   // 16384 threads
    int e  = idx & 1023;
    int b0 = (idx >> 10) * 4;
    const float* W = attn_W + Hdim + e;
    float a0 = 0.f, a1 = 0.f, a2 = 0.f, a3 = 0.f;
    #pragma unroll 4
    for (int hh = 0; hh < Hdim; hh++) {
        float w = W[(size_t)hh * (Hdim + EHdim)];
        a0 += g_h[(b0 + 0) * Hdim + hh] * w;
        a1 += g_h[(b0 + 1) * Hdim + hh] * w;
        a2 += g_h[(b0 + 2) * Hdim + hh] * w;
        a3 += g_h[(b0 + 3) * Hdim + hh] * w;
    }
    g_u[(b0 + 0) * EHdim + e] = a0;
    g_u[(b0 + 1) * EHdim + e] = a1;
    g_u[(b0 + 2) * EHdim + e] = a2;
    g_u[(b0 + 3) * EHdim + e] = a3;
}

// ---------------------------------------------------------------------------
// K3: scores[b,s] = dot(enc[s,b,:], u[b,:])  (per-b const dropped: softmax-invariant)
// ---------------------------------------------------------------------------
__global__ __launch_bounds__(256) void scores_kernel(const float* __restrict__ enc)
{
    int gw   = (blockIdx.x * blockDim.x + threadIdx.x) >> 5;
    int lane = threadIdx.x & 31;
    int b = gw >> 9;
    int s = gw & 511;
    const float4* ev = (const float4*)(enc + (size_t)s * (Bdim * EHdim) + (size_t)b * EHdim);
    const float4* uv = (const float4*)(g_u + (size_t)b * EHdim);
    float acc = 0.f;
    #pragma unroll 4
    for (int t = lane; t < EHdim / 4; t += 32) {
        float4 e4 = ev[t], u4 = uv[t];
        acc += e4.x*u4.x + e4.y*u4.y + e4.z*u4.z + e4.w*u4.w;
    }
    #pragma unroll
    for (int o = 16; o; o >>= 1) acc += __shfl_xor_sync(0xffffffffu, acc, o);
    if (lane == 0) g_scores[b * Sdim + s] = acc;
}

// ---------------------------------------------------------------------------
// K4: softmax over s (512) per b
// ---------------------------------------------------------------------------
__global__ __launch_bounds__(256) void softmax_kernel(float* __restrict__ out_attn)
{
    int b = blockIdx.x, tid = threadIdx.x;
    __shared__ float red[8];
    __shared__ float bcast[2];

    float s0 = g_scores[b * Sdim + tid];
    float s1 = g_scores[b * Sdim + 256 + tid];

    float m = fmaxf(s0, s1);
    #pragma unroll
    for (int o = 16; o; o >>= 1) m = fmaxf(m, __shfl_xor_sync(0xffffffffu, m, o));
    if ((tid & 31) == 0) red[tid >> 5] = m;
    __syncthreads();
    if (tid < 32) {
        float v = (tid < 8) ? red[tid] : -FLT_MAX;
        #pragma unroll
        for (int o = 4; o; o >>= 1) v = fmaxf(v, __shfl_xor_sync(0xffffffffu, v, o));
        if (tid == 0) bcast[0] = v;
    }
    __syncthreads();
    float bm = bcast[0];

    float e0 = expf(s0 - bm), e1 = expf(s1 - bm);
    float sum = e0 + e1;
    #pragma unroll
    for (int o = 16; o; o >>= 1) sum += __shfl_xor_sync(0xffffffffu, sum, o);
    if ((tid & 31) == 0) red[tid >> 5] = sum;
    __syncthreads();
    if (tid < 32) {
        float v = (tid < 8) ? red[tid] : 0.f;
        #pragma unroll
        for (int o = 4; o; o >>= 1) v += __shfl_xor_sync(0xffffffffu, v, o);
        if (tid == 0) bcast[1] = v;
    }
    __syncthreads();
    float inv = 1.f / bcast[1];

    float w0 = e0 * inv, w1 = e1 * inv;
    g_w[b * Sdim + tid]       = w0;
    g_w[b * Sdim + 256 + tid] = w1;
    out_attn[b * Sdim + tid]       = w0;
    out_attn[b * Sdim + 256 + tid] = w1;
}

// ---------------------------------------------------------------------------
// K5: context[b,e] = sum_s w[b,s] * enc[s,b,e]; writes g_y[:, Hdim:]
// ---------------------------------------------------------------------------
__global__ __launch_bounds__(256) void context_kernel(const float* __restrict__ enc)
{
    int idx = blockIdx.x * blockDim.x + threadIdx.x;   // 65536
    int b = idx >> 10;
    int e = idx & 1023;
    const float* wrow = g_w + b * Sdim;
    const float* ep   = enc + (size_t)b * EHdim + e;
    float a0 = 0.f, a1 = 0.f;
    #pragma unroll 4
    for (int s = 0; s < Sdim; s += 2) {
        a0 += wrow[s]     * ep[(size_t)s * (Bdim * EHdim)];
        a1 += wrow[s + 1] * ep[(size_t)(s + 1) * (Bdim * EHdim)];
    }
    g_y[(size_t)b * Ktot + Hdim + e] = a0 + a1;
}

// ---------------------------------------------------------------------------
// K6: dec = y @ out_W^T + out_b via mma.sync tf32 (m16n8k8), cp.async pipeline.
// CTA: D[128 v x 64 b]. 8 warps in 4(M) x 2(N); warp tile 32x32.
// K = 2048 in 32 chunks of 64, double-buffered smem.
// A = out_W rows (v), row-major; B = y rows (b), "col-major" k x n fragments.
// Smem rows padded to 68 floats -> frag loads hit all 32 banks exactly once.
// ---------------------------------------------------------------------------
#define DEC_M     128
#define DEC_KC    64
#define DEC_NCH   (Ktot / DEC_KC)       // 32
#define RSTR      68                    // padded row stride (floats)
#define AWORDS    (DEC_M * RSTR)        // 8704
#define BWORDS    (Bdim * RSTR)         // 4352
#define BUFWORDS  (AWORDS + BWORDS)     // 13056
#define DEC_SMEM  (2 * BUFWORDS * 4)    // 104448 bytes

__global__ __launch_bounds__(256, 1) void dec_kernel(
    const float* __restrict__ out_W, const float* __restrict__ out_b,
    float* __restrict__ dec)
{
    extern __shared__ float smf[];
    const uint32_t sb = smem_to_u32(smf);

    const int tx   = threadIdx.x;
    const int wid  = tx >> 5;
    const int lane = tx & 31;
    const int gid  = lane >> 2;      // 0..7
    const int tig  = lane & 3;       // 0..3
    const int wm   = wid & 3;        // 4 warps across M
    const int wn   = wid >> 2;       // 2 warps across N
    const int rb   = wm * 32;
    const int bb   = wn * 32;
    const int vb   = blockIdx.x * DEC_M;

    float acc[2][4][4];
    #pragma unroll
    for (int mt = 0; mt < 2; mt++)
        #pragma unroll
        for (int nt = 0; nt < 4; nt++)
            #pragma unroll
            for (int i = 0; i < 4; i++) acc[mt][nt][i] = 0.f;

    // ---- staging: chunk c -> buffer buf ----
    auto stage = [&](int c, int buf) {
        const int k0 = c * DEC_KC;
        const uint32_t base = sb + (uint32_t)buf * BUFWORDS * 4;
        #pragma unroll
        for (int i = 0; i < 8; i++) {            // A: 128 rows x 16 quads
            int idx = tx + 256 * i;
            int r = idx >> 4, q = idx & 15;
            int v = vb + r;
            int vc = v < Vdim ? v : (Vdim - 1);
            const float* src = out_W + (size_t)vc * Ktot + k0 + 4 * q;
            uint32_t dst = base + (uint32_t)(r * RSTR + 4 * q) * 4;
            cp_async16_zfill(dst, src, v < Vdim ? 16 : 0);
        }
        #pragma unroll
        for (int i = 0; i < 4; i++) {            // B: 64 rows x 16 quads
            int idx = tx + 256 * i;
            int r = idx >> 4, q = idx & 15;
            const float* src = g_y + (size_t)r * Ktot + k0 + 4 * q;
            uint32_t dst = base + (uint32_t)(AWORDS + r * RSTR + 4 * q) * 4;
            cp_async16(dst, src);
        }
    };

    stage(0, 0);
    CP_COMMIT();

    for (int c = 0; c < DEC_NCH; c++) {
        const int buf = c & 1;
        if (c + 1 < DEC_NCH) {
            stage(c + 1, (c + 1) & 1);
            CP_COMMIT();
            CP_WAIT(1);
        } else {
            CP_WAIT(0);
        }
        __syncthreads();

        const float* As = smf + buf * BUFWORDS;
        const float* Bs = As + AWORDS;
        #pragma unroll
        for (int ks = 0; ks < 8; ks++) {
            const int k = ks * 8;
            uint32_t a[2][4], bf[4][2];
            #pragma unroll
            for (int mt = 0; mt < 2; mt++) {
                int row = rb + mt * 16 + gid;
                a[mt][0] = f2tf32(As[row * RSTR + k + tig]);
                a[mt][1] = f2tf32(As[(row + 8) * RSTR + k + tig]);
                a[mt][2] = f2tf32(As[row * RSTR + k + tig + 4]);
                a[mt][3] = f2tf32(As[(row + 8) * RSTR + k + tig + 4]);
            }
            #pragma unroll
            for (int nt = 0; nt < 4; nt++) {
                int bc = bb + nt * 8 + gid;
                bf[nt][0] = f2tf32(Bs[bc * RSTR + k + tig]);
                bf[nt][1] = f2tf32(Bs[bc * RSTR + k + tig + 4]);
            }
            #pragma unroll
            for (int mt = 0; mt < 2; mt++)
                #pragma unroll
                for (int nt = 0; nt < 4; nt++)
                    mma_tf32(acc[mt][nt], a[mt], bf[nt]);
        }
        __syncthreads();
    }

    // ---- epilogue: acc -> dec[b][v] + out_b[v] ----
    #pragma unroll
    for (int mt = 0; mt < 2; mt++) {
        int v0 = vb + rb + mt * 16 + gid;
        int v1 = v0 + 8;
        float bias0 = (v0 < Vdim) ? out_b[v0] : 0.f;
        float bias1 = (v1 < Vdim) ? out_b[v1] : 0.f;
        #pragma unroll
        for (int nt = 0; nt < 4; nt++) {
            int b0 = bb + nt * 8 + 2 * tig;
            int b1 = b0 + 1;
            if (v0 < Vdim) {
                dec[(size_t)b0 * Vdim + v0] = acc[mt][nt][0] + bias0;
                dec[(size_t)b1 * Vdim + v0] = acc[mt][nt][1] + bias0;
            }
            if (v1 < Vdim) {
                dec[(size_t)b0 * Vdim + v1] = acc[mt][nt][2] + bias1;
                dec[(size_t)b1 * Vdim + v1] = acc[mt][nt][3] + bias1;
            }
        }
    }
}

// ---------------------------------------------------------------------------
// K7: in-place log_softmax over V per row b
// ---------------------------------------------------------------------------
__global__ __launch_bounds__(512) void logsoftmax_kernel(float* __restrict__ dec)
{
    int b = blockIdx.x, tid = threadIdx.x;
    float* row = dec + (size_t)b * Vdim;
    __shared__ float red[16];
    __shared__ float bcast;

    float m = -FLT_MAX;
    for (int i = tid; i < Vdim; i += 512) m = fmaxf(m, row[i]);
    #pragma unroll
    for (int o = 16; o; o >>= 1) m = fmaxf(m, __shfl_xor_sync(0xffffffffu, m, o));
    if ((tid & 31) == 0) red[tid >> 5] = m;
    __syncthreads();
    if (tid < 32) {
        float v = (tid < 16) ? red[tid] : -FLT_MAX;
        #pragma unroll
        for (int o = 8; o; o >>= 1) v = fmaxf(v, __shfl_xor_sync(0xffffffffu, v, o));
        if (tid == 0) bcast = v;
    }
    __syncthreads();
    float bm = bcast;
    __syncthreads();

    float s = 0.f;
    for (int i = tid; i < Vdim; i += 512) s += expf(row[i] - bm);
    #pragma unroll
    for (int o = 16; o; o >>= 1) s += __shfl_xor_sync(0xffffffffu, s, o);
    if ((tid & 31) == 0) red[tid >> 5] = s;
    __syncthreads();
    if (tid < 32) {
        float v = (tid < 16) ? red[tid] : 0.f;
        #pragma unroll
        for (int o = 8; o; o >>= 1) v += __shfl_xor_sync(0xffffffffu, v, o);
        if (tid == 0) bcast = v;
    }
    __syncthreads();
    float lse = bm + logf(bcast);

    for (int i = tid; i < Vdim; i += 512) row[i] -= lse;
}

// ---------------------------------------------------------------------------
extern "C" void kernel_launch(void* const* d_in, const int* in_sizes, int n_in,
                              void* d_out, int out_size)
{
    const float* x      = (const float*)d_in[0];   // input_seq (1,B,I)
    const float* enc    = (const float*)d_in[1];   // encoder_outputs (S,B,EH)
    const float* W_ih   = (const float*)d_in[3];
    const float* b_ih   = (const float*)d_in[5];
    const float* b_hh   = (const float*)d_in[6];
    const float* attn_W = (const float*)d_in[7];
    const float* out_W  = (const float*)d_in[9];
    const float* out_b  = (const float*)d_in[10];

    float* out = (float*)d_out;
    const size_t OFF_H    = (size_t)Bdim * Vdim;
    const size_t OFF_ATTN = OFF_H + (size_t)Bdim * Hdim;

    cudaFuncSetAttribute(dec_kernel, cudaFuncAttributeMaxDynamicSharedMemorySize, DEC_SMEM);

    gru_kernel<<<128, 256>>>(x, W_ih, b_ih, b_hh, out + OFF_H);
    u_kernel<<<64, 256>>>(attn_W);
    scores_kernel<<<4096, 256>>>(enc);
    softmax_kernel<<<Bdim, 256>>>(out + OFF_ATTN);
    context_kernel<<<256, 256>>>(enc);
    dec_kernel<<<(Vdim + DEC_M - 1) / DEC_M, 256, DEC_SMEM>>>(out_W, out_b, out);
    logsoftmax_kernel<<<Bdim, 512>>>(out);
}

// round 6
// speedup vs baseline: 2.6786x; 1.5249x over previous
#include <cuda_runtime.h>
#include <cstdint>
#include <cfloat>

#define Sdim 512
#define Bdim 64
#define Hdim 1024
#define EHdim 1024
#define Vdim 50257
#define Ktot 2048              // H + EH

// ---- scratch (no allocations allowed) ----
__device__ float g_h[Bdim * Hdim];
__device__ float g_u[Bdim * EHdim];
__device__ float g_scores[Bdim * Sdim];
__device__ float g_w[Bdim * Sdim];
__device__ float g_y[Bdim * Ktot];   // [h | context], K-major per b

// ============================================================================
// sm_80-class PTX helpers (safe under .target sm_103 — no 'a' features)
// ============================================================================
__device__ __forceinline__ uint32_t smem_to_u32(const void* p) {
    uint32_t a;
    asm("{ .reg .u64 t; cvta.to.shared.u64 t, %1; cvt.u32.u64 %0, t; }" : "=r"(a) : "l"(p));
    return a;
}
__device__ __forceinline__ void cp_async16(uint32_t dst, const void* src) {
    asm volatile("cp.async.ca.shared.global [%0], [%1], 16;" :: "r"(dst), "l"(src));
}
__device__ __forceinline__ void cp_async16_zfill(uint32_t dst, const void* src, int src_bytes) {
    asm volatile("cp.async.ca.shared.global [%0], [%1], 16, %2;"
                 :: "r"(dst), "l"(src), "r"(src_bytes));
}
#define CP_COMMIT() asm volatile("cp.async.commit_group;" ::: "memory")
#define CP_WAIT(n)  asm volatile("cp.async.wait_group %0;" :: "n"(n) : "memory")

__device__ __forceinline__ void mma_tf32(float* c, const uint32_t* a, const uint32_t* b) {
    asm volatile("mma.sync.aligned.m16n8k8.row.col.f32.tf32.tf32.f32 "
        "{%0,%1,%2,%3}, {%4,%5,%6,%7}, {%8,%9}, {%0,%1,%2,%3};"
        : "+f"(c[0]), "+f"(c[1]), "+f"(c[2]), "+f"(c[3])
        : "r"(a[0]), "r"(a[1]), "r"(a[2]), "r"(a[3]), "r"(b[0]), "r"(b[1]));
}

// ---------------------------------------------------------------------------
// K1: GRU with h0=0 => gh = b_hh. Tiled GEMM: block = 8 j x 64 b, K via smem.
// ---------------------------------------------------------------------------
__global__ __launch_bounds__(256) void gru_kernel(
    const float* __restrict__ x, const float* __restrict__ W_ih,
    const float* __restrict__ b_ih, const float* __restrict__ b_hh,
    float* __restrict__ out_h)
{
    __shared__ float w_s[24][33];
    __shared__ float x_s[32][65];

    const int t  = threadIdx.x;
    const int j0 = blockIdx.x * 8;
    const int jj = t & 7;
    const int bg = t >> 3;

    float a00 = 0.f, a01 = 0.f, a10 = 0.f, a11 = 0.f, a20 = 0.f, a21 = 0.f;

    for (int k0 = 0; k0 < Hdim; k0 += 32) {
        if (t < 192) {
            int r = t >> 3, f4 = t & 7;
            int g = r >> 3, jl = r & 7;
            float4 w = *(const float4*)(W_ih + (size_t)(g * Hdim + j0 + jl) * Hdim + k0 + 4 * f4);
            w_s[r][4 * f4 + 0] = w.x; w_s[r][4 * f4 + 1] = w.y;
            w_s[r][4 * f4 + 2] = w.z; w_s[r][4 * f4 + 3] = w.w;
        }
        #pragma unroll
        for (int i = 0; i < 2; i++) {
            int idx = t + 256 * i;
            int b = idx >> 3, q = idx & 7;
            float4 xv = *(const float4*)(x + (size_t)b * Hdim + k0 + 4 * q);
            x_s[4 * q + 0][b] = xv.x; x_s[4 * q + 1][b] = xv.y;
            x_s[4 * q + 2][b] = xv.z; x_s[4 * q + 3][b] = xv.w;
        }
        __syncthreads();
        #pragma unroll
        for (int kk = 0; kk < 32; kk++) {
            float x0 = x_s[kk][2 * bg], x1 = x_s[kk][2 * bg + 1];
            float w0 = w_s[jj][kk], w1 = w_s[8 + jj][kk], w2 = w_s[16 + jj][kk];
            a00 += w0 * x0; a01 += w0 * x1;
            a10 += w1 * x0; a11 += w1 * x1;
            a20 += w2 * x0; a21 += w2 * x1;
        }
        __syncthreads();
    }

    int j = j0 + jj;
    float bi0 = b_ih[j], bi1 = b_ih[Hdim + j], bi2 = b_ih[2 * Hdim + j];
    float bh0 = b_hh[j], bh1 = b_hh[Hdim + j], bh2 = b_hh[2 * Hdim + j];
    #pragma unroll
    for (int q = 0; q < 2; q++) {
        int b = 2 * bg + q;
        float xr = (q ? a01 : a00) + bi0;
        float xz = (q ? a11 : a10) + bi1;
        float xn = (q ? a21 : a20) + bi2;
        float r = 1.f / (1.f + expf(-(xr + bh0)));
        float z = 1.f / (1.f + expf(-(xz + bh1)));
        float n = tanhf(xn + r * bh2);
        float h = (1.f - z) * n;               // + z*h0, h0 = 0
        g_h[b * Hdim + j] = h;
        g_y[(size_t)b * Ktot + j] = h;
        out_h[b * Hdim + j] = h;
    }
}

// ---------------------------------------------------------------------------
// K2: u[b,e] = sum_h g_h[b,h] * attn_W[h, Hdim + e]
// thread per (e,b): 65536 threads (4x prior parallelism); W reuse via L2.
// ---------------------------------------------------------------------------
__global__ __launch_bounds__(256) void u_kernel(const float* __restrict__ attn_W)
{
    int idx = blockIdx.x * blockDim.x + threadIdx.x;   // 65536
    int e = idx & 1023;
    int b = idx >> 10;
    const float* W = attn_W + Hdim + e;
    const float* hb = g_h + b * Hdim;
    float a0 = 0.f, a1 = 0.f;
    #pragma unroll 8
    for (int hh = 0; hh < Hdim; hh += 2) {
        a0 += hb[hh]     * W[(size_t)hh * (Hdim + EHdim)];
        a1 += hb[hh + 1] * W[(size_t)(hh + 1) * (Hdim + EHdim)];
    }
    g_u[b * EHdim + e] = a0 + a1;
}

// ---------------------------------------------------------------------------
// K3: scores[b,s] = dot(enc[s,b,:], u[b,:])
// ---------------------------------------------------------------------------
__global__ __launch_bounds__(256) void scores_kernel(const float* __restrict__ enc)
{
    int gw   = (blockIdx.x * blockDim.x + threadIdx.x) >> 5;
    int lane = threadIdx.x & 31;
    int b = gw >> 9;
    int s = gw & 511;
    const float4* ev = (const float4*)(enc + (size_t)s * (Bdim * EHdim) + (size_t)b * EHdim);
    const float4* uv = (const float4*)(g_u + (size_t)b * EHdim);
    float acc = 0.f;
    #pragma unroll 4
    for (int t = lane; t < EHdim / 4; t += 32) {
        float4 e4 = ev[t], u4 = uv[t];
        acc += e4.x*u4.x + e4.y*u4.y + e4.z*u4.z + e4.w*u4.w;
    }
    #pragma unroll
    for (int o = 16; o; o >>= 1) acc += __shfl_xor_sync(0xffffffffu, acc, o);
    if (lane == 0) g_scores[b * Sdim + s] = acc;
}

// ---------------------------------------------------------------------------
// K4: softmax over s (512) per b
// ---------------------------------------------------------------------------
__global__ __launch_bounds__(256) void softmax_kernel(float* __restrict__ out_attn)
{
    int b = blockIdx.x, tid = threadIdx.x;
    __shared__ float red[8];
    __shared__ float bcast[2];

    float s0 = g_scores[b * Sdim + tid];
    float s1 = g_scores[b * Sdim + 256 + tid];

    float m = fmaxf(s0, s1);
    #pragma unroll
    for (int o = 16; o; o >>= 1) m = fmaxf(m, __shfl_xor_sync(0xffffffffu, m, o));
    if ((tid & 31) == 0) red[tid >> 5] = m;
    __syncthreads();
    if (tid < 32) {
        float v = (tid < 8) ? red[tid] : -FLT_MAX;
        #pragma unroll
        for (int o = 4; o; o >>= 1) v = fmaxf(v, __shfl_xor_sync(0xffffffffu, v, o));
        if (tid == 0) bcast[0] = v;
    }
    __syncthreads();
    float bm = bcast[0];

    float e0 = expf(s0 - bm), e1 = expf(s1 - bm);
    float sum = e0 + e1;
    #pragma unroll
    for (int o = 16; o; o >>= 1) sum += __shfl_xor_sync(0xffffffffu, sum, o);
    if ((tid & 31) == 0) red[tid >> 5] = sum;
    __syncthreads();
    if (tid < 32) {
        float v = (tid < 8) ? red[tid] : 0.f;
        #pragma unroll
        for (int o = 4; o; o >>= 1) v += __shfl_xor_sync(0xffffffffu, v, o);
        if (tid == 0) bcast[1] = v;
    }
    __syncthreads();
    float inv = 1.f / bcast[1];

    float w0 = e0 * inv, w1 = e1 * inv;
    g_w[b * Sdim + tid]       = w0;
    g_w[b * Sdim + 256 + tid] = w1;
    out_attn[b * Sdim + tid]       = w0;
    out_attn[b * Sdim + 256 + tid] = w1;
}

// ---------------------------------------------------------------------------
// K5: context[b,e] = sum_s w[b,s] * enc[s,b,e]
// ---------------------------------------------------------------------------
__global__ __launch_bounds__(256) void context_kernel(const float* __restrict__ enc)
{
    int idx = blockIdx.x * blockDim.x + threadIdx.x;   // 65536
    int b = idx >> 10;
    int e = idx & 1023;
    const float* wrow = g_w + b * Sdim;
    const float* ep   = enc + (size_t)b * EHdim + e;
    float a0 = 0.f, a1 = 0.f;
    #pragma unroll 4
    for (int s = 0; s < Sdim; s += 2) {
        a0 += wrow[s]     * ep[(size_t)s * (Bdim * EHdim)];
        a1 += wrow[s + 1] * ep[(size_t)(s + 1) * (Bdim * EHdim)];
    }
    g_y[(size_t)b * Ktot + Hdim + e] = a0 + a1;
}

// ---------------------------------------------------------------------------
// K6: dec = y @ out_W^T + out_b via mma.sync tf32 (m16n8k8), cp.async pipeline.
// CTA: D[128 v x 64 b]; 8 warps 4(M)x2(N), warp tile 32x32.
// K = 2048 in 32 chunks of 64, double-buffered smem; 2 CTAs/SM.
// tf32 operands are raw fp32 bits (HW truncation) — no cvt in hot loop.
// ---------------------------------------------------------------------------
#define DEC_M     128
#define DEC_KC    64
#define DEC_NCH   (Ktot / DEC_KC)       // 32
#define RSTR      68                    // padded row stride (floats)
#define AWORDS    (DEC_M * RSTR)        // 8704
#define BWORDS    (Bdim * RSTR)         // 4352
#define BUFWORDS  (AWORDS + BWORDS)     // 13056
#define DEC_SMEM  (2 * BUFWORDS * 4)    // 104448 bytes

__global__ __launch_bounds__(256, 2) void dec_kernel(
    const float* __restrict__ out_W, const float* __restrict__ out_b,
    float* __restrict__ dec)
{
    extern __shared__ float smf[];
    const uint32_t sb = smem_to_u32(smf);

    const int tx   = threadIdx.x;
    const int wid  = tx >> 5;
    const int lane = tx & 31;
    const int gid  = lane >> 2;      // 0..7
    const int tig  = lane & 3;       // 0..3
    const int wm   = wid & 3;        // 4 warps across M
    const int wn   = wid >> 2;       // 2 warps across N
    const int rb   = wm * 32;
    const int bb   = wn * 32;
    const int vb   = blockIdx.x * DEC_M;

    float acc[2][4][4];
    #pragma unroll
    for (int mt = 0; mt < 2; mt++)
        #pragma unroll
        for (int nt = 0; nt < 4; nt++)
            #pragma unroll
            for (int i = 0; i < 4; i++) acc[mt][nt][i] = 0.f;

    auto stage = [&](int c, int buf) {
        const int k0 = c * DEC_KC;
        const uint32_t base = sb + (uint32_t)buf * BUFWORDS * 4;
        #pragma unroll
        for (int i = 0; i < 8; i++) {            // A: 128 rows x 16 quads
            int idx = tx + 256 * i;
            int r = idx >> 4, q = idx & 15;
            int v = vb + r;
            int vc = v < Vdim ? v : (Vdim - 1);
            const float* src = out_W + (size_t)vc * Ktot + k0 + 4 * q;
            uint32_t dst = base + (uint32_t)(r * RSTR + 4 * q) * 4;
            cp_async16_zfill(dst, src, v < Vdim ? 16 : 0);
        }
        #pragma unroll
        for (int i = 0; i < 4; i++) {            // B: 64 rows x 16 quads
            int idx = tx + 256 * i;
            int r = idx >> 4, q = idx & 15;
            const float* src = g_y + (size_t)r * Ktot + k0 + 4 * q;
            uint32_t dst = base + (uint32_t)(AWORDS + r * RSTR + 4 * q) * 4;
            cp_async16(dst, src);
        }
    };

    stage(0, 0);
    CP_COMMIT();

    for (int c = 0; c < DEC_NCH; c++) {
        const int buf = c & 1;
        if (c + 1 < DEC_NCH) {
            stage(c + 1, (c + 1) & 1);
            CP_COMMIT();
            CP_WAIT(1);
        } else {
            CP_WAIT(0);
        }
        __syncthreads();

        const float* As = smf + buf * BUFWORDS;
        const float* Bs = As + AWORDS;
        #pragma unroll
        for (int ks = 0; ks < 8; ks++) {
            const int k = ks * 8;
            uint32_t a[2][4], bf[4][2];
            #pragma unroll
            for (int mt = 0; mt < 2; mt++) {
                int row = rb + mt * 16 + gid;
                a[mt][0] = __float_as_uint(As[row * RSTR + k + tig]);
                a[mt][1] = __float_as_uint(As[(row + 8) * RSTR + k + tig]);
                a[mt][2] = __float_as_uint(As[row * RSTR + k + tig + 4]);
                a[mt][3] = __float_as_uint(As[(row + 8) * RSTR + k + tig + 4]);
            }
            #pragma unroll
            for (int nt = 0; nt < 4; nt++) {
                int bc = bb + nt * 8 + gid;
                bf[nt][0] = __float_as_uint(Bs[bc * RSTR + k + tig]);
                bf[nt][1] = __float_as_uint(Bs[bc * RSTR + k + tig + 4]);
            }
            #pragma unroll
            for (int mt = 0; mt < 2; mt++)
                #pragma unroll
                for (int nt = 0; nt < 4; nt++)
                    mma_tf32(acc[mt][nt], a[mt], bf[nt]);
        }
        __syncthreads();
    }

    // ---- epilogue ----
    #pragma unroll
    for (int mt = 0; mt < 2; mt++) {
        int v0 = vb + rb + mt * 16 + gid;
        int v1 = v0 + 8;
        float bias0 = (v0 < Vdim) ? out_b[v0] : 0.f;
        float bias1 = (v1 < Vdim) ? out_b[v1] : 0.f;
        #pragma unroll
        for (int nt = 0; nt < 4; nt++) {
            int b0 = bb + nt * 8 + 2 * tig;
            int b1 = b0 + 1;
            if (v0 < Vdim) {
                dec[(size_t)b0 * Vdim + v0] = acc[mt][nt][0] + bias0;
                dec[(size_t)b1 * Vdim + v0] = acc[mt][nt][1] + bias0;
            }
            if (v1 < Vdim) {
                dec[(size_t)b0 * Vdim + v1] = acc[mt][nt][2] + bias1;
                dec[(size_t)b1 * Vdim + v1] = acc[mt][nt][3] + bias1;
            }
        }
    }
}

// ---------------------------------------------------------------------------
// K7: in-place log_softmax over V per row b
// ---------------------------------------------------------------------------
__global__ __launch_bounds__(512) void logsoftmax_kernel(float* __restrict__ dec)
{
    int b = blockIdx.x, tid = threadIdx.x;
    float* row = dec + (size_t)b * Vdim;
    __shared__ float red[16];
    __shared__ float bcast;

    float m = -FLT_MAX;
    for (int i = tid; i < Vdim; i += 512) m = fmaxf(m, row[i]);
    #pragma unroll
    for (int o = 16; o; o >>= 1) m = fmaxf(m, __shfl_xor_sync(0xffffffffu, m, o));
    if ((tid & 31) == 0) red[tid >> 5] = m;
    __syncthreads();
    if (tid < 32) {
        float v = (tid < 16) ? red[tid] : -FLT_MAX;
        #pragma unroll
        for (int o = 8; o; o >>= 1) v = fmaxf(v, __shfl_xor_sync(0xffffffffu, v, o));
        if (tid == 0) bcast = v;
    }
    __syncthreads();
    float bm = bcast;
    __syncthreads();

    float s = 0.f;
    for (int i = tid; i < Vdim; i += 512) s += expf(row[i] - bm);
    #pragma unroll
    for (int o = 16; o; o >>= 1) s += __shfl_xor_sync(0xffffffffu, s, o);
    if ((tid & 31) == 0) red[tid >> 5] = s;
    __syncthreads();
    if (tid < 32) {
        float v = (tid < 16) ? red[tid] : 0.f;
        #pragma unroll
        for (int o = 8; o; o >>= 1) v += __shfl_xor_sync(0xffffffffu, v, o);
        if (tid == 0) bcast = v;
    }
    __syncthreads();
    float lse = bm + logf(bcast);

    for (int i = tid; i < Vdim; i += 512) row[i] -= lse;
}

// ---------------------------------------------------------------------------
extern "C" void kernel_launch(void* const* d_in, const int* in_sizes, int n_in,
                              void* d_out, int out_size)
{
    const float* x      = (const float*)d_in[0];
    const float* enc    = (const float*)d_in[1];
    const float* W_ih   = (const float*)d_in[3];
    const float* b_ih   = (const float*)d_in[5];
    const float* b_hh   = (const float*)d_in[6];
    const float* attn_W = (const float*)d_in[7];
    const float* out_W  = (const float*)d_in[9];
    const float* out_b  = (const float*)d_in[10];

    float* out = (float*)d_out;
    const size_t OFF_H    = (size_t)Bdim * Vdim;
    const size_t OFF_ATTN = OFF_H + (size_t)Bdim * Hdim;

    cudaFuncSetAttribute(dec_kernel, cudaFuncAttributeMaxDynamicSharedMemorySize, DEC_SMEM);

    gru_kernel<<<128, 256>>>(x, W_ih, b_ih, b_hh, out + OFF_H);
    u_kernel<<<256, 256>>>(attn_W);
    scores_kernel<<<4096, 256>>>(enc);
    softmax_kernel<<<Bdim, 256>>>(out + OFF_ATTN);
    context_kernel<<<256, 256>>>(enc);
    dec_kernel<<<(Vdim + DEC_M - 1) / DEC_M, 256, DEC_SMEM>>>(out_W, out_b, out);
    logsoftmax_kernel<<<Bdim, 512>>>(out);
}